// round 1
// baseline (speedup 1.0000x reference)
#include <cuda_runtime.h>
#include <cstdint>
#include <math.h>

#define NLEVELS 16

__global__ void __launch_bounds__(256) hash_enc_kernel(
    const float* __restrict__ positions,
    const float* __restrict__ table,
    float* __restrict__ out,
    int n)
{
    // Level constants derived from the reference's _level_constants():
    //   res:   16,22,28,37,49,65 dense; levels 6..15 hashed (size 2^19)
    //   sizes: res^3 rounded up to multiple of 8, capped at 2^19
    constexpr unsigned RES[6]  = {16u, 22u, 28u, 37u, 49u, 65u};
    constexpr unsigned SIZE[6] = {4096u, 10648u, 21952u, 50656u, 117656u, 274632u};
    constexpr unsigned OFF[NLEVELS] = {
        0u, 4096u, 14744u, 36696u, 87352u, 205008u, 479640u,
        1003928u, 1528216u, 2052504u, 2576792u, 3101080u,
        3625368u, 4149656u, 4673944u, 5198232u};
    constexpr unsigned HASH_MASK = 524287u;  // 2^19 - 1
    constexpr unsigned P1 = 2654435761u;
    constexpr unsigned P2 = 805459861u;

    // scale_l = 16 * exp(l * ln(B_SCALE)) - 1, computed in double for accuracy.
    // ln(B_SCALE) = ln(float32(2^0.4)) = 0.4*ln2 + 3.46583457e-8
    __shared__ float s_scale[NLEVELS];
    if (threadIdx.x < NLEVELS) {
        const double LNB = 0.27725890688232382;
        s_scale[threadIdx.x] =
            (float)(16.0 * exp((double)threadIdx.x * LNB) - 1.0);
    }
    __syncthreads();

    int p = blockIdx.x * blockDim.x + threadIdx.x;
    if (p >= n) return;

    const float px = positions[3 * p + 0];
    const float py = positions[3 * p + 1];
    const float pz = positions[3 * p + 2];

    const float2* __restrict__ tab2 = reinterpret_cast<const float2*>(table);

    float acc[2 * NLEVELS];

    #pragma unroll
    for (int l = 0; l < NLEVELS; ++l) {
        const float s = s_scale[l];
        float fx = px * s + 0.5f;
        float fy = py * s + 0.5f;
        float fz = pz * s + 0.5f;
        float gxf = floorf(fx), gyf = floorf(fy), gzf = floorf(fz);
        float rx = fx - gxf, ry = fy - gyf, rz = fz - gzf;
        unsigned gx = (unsigned)gxf, gy = (unsigned)gyf, gz = (unsigned)gzf;
        float wx0 = 1.0f - rx, wy0 = 1.0f - ry, wz0 = 1.0f - rz;

        unsigned tx0, tx1, ty0, ty1, tz0, tz1;
        if (l < 6) {
            unsigned r  = RES[l];
            unsigned r2 = RES[l] * RES[l];
            tx0 = gx;       tx1 = gx + 1u;
            ty0 = gy * r;   ty1 = ty0 + r;
            tz0 = gz * r2;  tz1 = tz0 + r2;
        } else {
            tx0 = gx;        tx1 = gx + 1u;
            ty0 = gy * P1;   ty1 = ty0 + P1;
            tz0 = gz * P2;   tz1 = tz0 + P2;
        }

        float a0 = 0.0f, a1 = 0.0f;
        #pragma unroll
        for (int c = 0; c < 8; ++c) {
            unsigned cx = (c & 1) ? tx1 : tx0;
            unsigned cy = (c & 2) ? ty1 : ty0;
            unsigned cz = (c & 4) ? tz1 : tz0;
            unsigned idx;
            if (l < 6) {
                idx = cx + cy + cz;              // under-hash: x + y*res + z*res^2
                if (idx >= SIZE[l]) idx -= SIZE[l];  // under < 2*size always
            } else {
                idx = (cx ^ cy ^ cz) & HASH_MASK;    // fast spatial hash
            }
            float2 f = __ldg(tab2 + (OFF[l] + idx));
            float w = ((c & 1) ? rx : wx0)
                    * ((c & 2) ? ry : wy0)
                    * ((c & 4) ? rz : wz0);
            a0 = fmaf(w, f.x, a0);
            a1 = fmaf(w, f.y, a1);
        }
        acc[2 * l]     = a0;
        acc[2 * l + 1] = a1;
    }

    float4* o4 = reinterpret_cast<float4*>(out + (size_t)p * (2 * NLEVELS));
    #pragma unroll
    for (int i = 0; i < 8; ++i)
        o4[i] = make_float4(acc[4 * i], acc[4 * i + 1],
                            acc[4 * i + 2], acc[4 * i + 3]);
}

extern "C" void kernel_launch(void* const* d_in, const int* in_sizes, int n_in,
                              void* d_out, int out_size)
{
    const float* positions = (const float*)d_in[0];
    const float* table     = (const float*)d_in[1];
    // Defensive: positions (N*3 = 3.1M floats) is smaller than table (11.4M floats)
    if (n_in >= 2 && in_sizes[0] > in_sizes[1]) {
        positions = (const float*)d_in[1];
        table     = (const float*)d_in[0];
    }
    float* out = (float*)d_out;
    int n = (in_sizes[0] > in_sizes[1] ? in_sizes[1] : in_sizes[0]) / 3;

    int threads = 256;
    int blocks  = (n + threads - 1) / threads;
    hash_enc_kernel<<<blocks, threads>>>(positions, table, out, n);
}

// round 5
// speedup vs baseline: 1.2086x; 1.2086x over previous
#include <cuda_runtime.h>
#include <cstdint>
#include <math.h>

#define NLEVELS 16

__global__ void __launch_bounds__(256) hash_enc_kernel(
    const float* __restrict__ positions,
    const float* __restrict__ table,
    float* __restrict__ out,
    int n)
{
    // Level constants derived from the reference's _level_constants():
    //   res: 16,22,28,37,49,65 dense; levels 6..15 hashed (size 2^19)
    constexpr unsigned RES[6]  = {16u, 22u, 28u, 37u, 49u, 65u};
    constexpr unsigned SIZE[6] = {4096u, 10648u, 21952u, 50656u, 117656u, 274632u};
    constexpr unsigned OFF[NLEVELS] = {
        0u, 4096u, 14744u, 36696u, 87352u, 205008u, 479640u,
        1003928u, 1528216u, 2052504u, 2576792u, 3101080u,
        3625368u, 4149656u, 4673944u, 5198232u};
    constexpr unsigned HASH_MASK = 524287u;  // 2^19 - 1
    constexpr unsigned P1 = 2654435761u;
    constexpr unsigned P2 = 805459861u;

    // scale_l = 16 * exp(l * ln(B_SCALE)) - 1 in double for accuracy.
    __shared__ float s_scale[NLEVELS];
    if (threadIdx.x < NLEVELS) {
        const double LNB = 0.27725890688232382;  // ln(float32(2^0.4))
        s_scale[threadIdx.x] =
            (float)(16.0 * exp((double)threadIdx.x * LNB) - 1.0);
    }
    __syncthreads();

    int p = blockIdx.x * blockDim.x + threadIdx.x;
    if (p >= n) return;

    const float px = positions[3 * p + 0];
    const float py = positions[3 * p + 1];
    const float pz = positions[3 * p + 2];

    const float2* __restrict__ tab2 = reinterpret_cast<const float2*>(table);

    float acc[2 * NLEVELS];

    #pragma unroll
    for (int l = 0; l < NLEVELS; ++l) {
        const float s = s_scale[l];
        float fx = px * s + 0.5f;
        float fy = py * s + 0.5f;
        float fz = pz * s + 0.5f;
        float gxf = floorf(fx), gyf = floorf(fy), gzf = floorf(fz);
        float rx = fx - gxf, ry = fy - gyf, rz = fz - gzf;
        unsigned gx = (unsigned)gxf, gy = (unsigned)gyf, gz = (unsigned)gzf;
        float wx0 = 1.0f - rx, wy0 = 1.0f - ry, wz0 = 1.0f - rz;

        unsigned ty0, ty1, tz0, tz1;
        if (l < 6) {
            unsigned r  = RES[l];
            unsigned r2 = RES[l] * RES[l];
            ty0 = gy * r;   ty1 = ty0 + r;
            tz0 = gz * r2;  tz1 = tz0 + r2;
        } else {
            ty0 = gy * P1;  ty1 = ty0 + P1;
            tz0 = gz * P2;  tz1 = tz0 + P2;
        }

        float a0 = 0.0f, a1 = 0.0f;
        // 4 (y,z) combos; for each, the x-pair (gx, gx+1) is fetched with one
        // aligned LDG.128 covering the aligned entry pair {e0&~1, e0|1};
        // the second corner needs a fallback LDG.64 only when it falls
        // outside that pair (odd e0 for dense, odd gx for hashed).
        #pragma unroll
        for (int yz = 0; yz < 4; ++yz) {
            unsigned cy = (yz & 1) ? ty1 : ty0;
            unsigned cz = (yz & 2) ? tz1 : tz0;
            float wyz = ((yz & 1) ? ry : wy0) * ((yz & 2) ? rz : wz0);

            unsigned e0, e1;
            if (l < 6) {
                unsigned u = gx + cy + cz;              // under-hash, < 2*SIZE
                e0 = (u >= SIZE[l]) ? u - SIZE[l] : u;
                unsigned u1 = u + 1u;
                e1 = (u1 >= SIZE[l]) ? u1 - SIZE[l] : u1;
            } else {
                unsigned h = cy ^ cz;
                e0 = (gx ^ h) & HASH_MASK;
                e1 = ((gx + 1u) ^ h) & HASH_MASK;
            }
            unsigned base = e0 & ~1u;
            float4 q = __ldg(reinterpret_cast<const float4*>(
                                 tab2 + (OFF[l] + base)));
            float f0x = (e0 & 1u) ? q.z : q.x;
            float f0y = (e0 & 1u) ? q.w : q.y;
            float f1x, f1y;
            if ((e1 & ~1u) == base) {
                f1x = (e1 & 1u) ? q.z : q.x;
                f1y = (e1 & 1u) ? q.w : q.y;
            } else {
                float2 f1 = __ldg(tab2 + (OFF[l] + e1));
                f1x = f1.x; f1y = f1.y;
            }
            float wx0yz = wx0 * wyz;
            float rxyz  = rx  * wyz;
            a0 = fmaf(wx0yz, f0x, a0);
            a1 = fmaf(wx0yz, f0y, a1);
            a0 = fmaf(rxyz,  f1x, a0);
            a1 = fmaf(rxyz,  f1y, a1);
        }
        acc[2 * l]     = a0;
        acc[2 * l + 1] = a1;
    }

    float4* o4 = reinterpret_cast<float4*>(out + (size_t)p * (2 * NLEVELS));
    #pragma unroll
    for (int i = 0; i < 8; ++i)
        o4[i] = make_float4(acc[4 * i], acc[4 * i + 1],
                            acc[4 * i + 2], acc[4 * i + 3]);
}

extern "C" void kernel_launch(void* const* d_in, const int* in_sizes, int n_in,
                              void* d_out, int out_size)
{
    const float* positions = (const float*)d_in[0];
    const float* table     = (const float*)d_in[1];
    if (n_in >= 2 && in_sizes[0] > in_sizes[1]) {
        positions = (const float*)d_in[1];
        table     = (const float*)d_in[0];
    }
    float* out = (float*)d_out;
    int n = (in_sizes[0] > in_sizes[1] ? in_sizes[1] : in_sizes[0]) / 3;

    int threads = 256;
    int blocks  = (n + threads - 1) / threads;
    hash_enc_kernel<<<blocks, threads>>>(positions, table, out, n);
}

// round 16
// speedup vs baseline: 1.2466x; 1.0315x over previous
#include <cuda_runtime.h>
#include <cstdint>
#include <math.h>

#define NLEVELS 16
#define STRIDE 33  // smem row stride in floats (32 + 1 pad, conflict-free)

__global__ void __launch_bounds__(256) hash_enc_kernel(
    const float* __restrict__ positions,
    const float* __restrict__ table,
    float* __restrict__ out,
    int n)
{
    // Level constants derived from the reference's _level_constants():
    //   res: 16,22,28,37,49,65 dense; levels 6..15 hashed (size 2^19)
    constexpr unsigned RES[6]  = {16u, 22u, 28u, 37u, 49u, 65u};
    constexpr unsigned SIZE[6] = {4096u, 10648u, 21952u, 50656u, 117656u, 274632u};
    constexpr unsigned OFF[NLEVELS] = {
        0u, 4096u, 14744u, 36696u, 87352u, 205008u, 479640u,
        1003928u, 1528216u, 2052504u, 2576792u, 3101080u,
        3625368u, 4149656u, 4673944u, 5198232u};
    constexpr unsigned HASH_MASK = 524287u;  // 2^19 - 1
    constexpr unsigned P1 = 2654435761u;
    constexpr unsigned P2 = 805459861u;

    __shared__ float s_scale[NLEVELS];
    __shared__ float s_stage[256 * STRIDE];  // per-warp 32x32 staging, stride 33

    if (threadIdx.x < NLEVELS) {
        const double LNB = 0.27725890688232382;  // ln(float32(2^0.4))
        s_scale[threadIdx.x] =
            (float)(16.0 * exp((double)threadIdx.x * LNB) - 1.0);
    }
    __syncthreads();

    int tid = threadIdx.x;
    int p = blockIdx.x * blockDim.x + tid;
    bool active = (p < n);

    float px = 0.f, py = 0.f, pz = 0.f;
    if (active) {
        px = positions[3 * p + 0];
        py = positions[3 * p + 1];
        pz = positions[3 * p + 2];
    }

    const float2* __restrict__ tab2 = reinterpret_cast<const float2*>(table);

    float acc[2 * NLEVELS];

    #pragma unroll
    for (int l = 0; l < NLEVELS; ++l) {
        const float s = s_scale[l];
        float fx = px * s + 0.5f;
        float fy = py * s + 0.5f;
        float fz = pz * s + 0.5f;
        float gxf = floorf(fx), gyf = floorf(fy), gzf = floorf(fz);
        float rx = fx - gxf, ry = fy - gyf, rz = fz - gzf;
        unsigned gx = (unsigned)gxf, gy = (unsigned)gyf, gz = (unsigned)gzf;
        float wx0 = 1.0f - rx, wy0 = 1.0f - ry, wz0 = 1.0f - rz;

        unsigned ty0, ty1, tz0, tz1;
        if (l < 6) {
            unsigned r  = RES[l];
            unsigned r2 = RES[l] * RES[l];
            ty0 = gy * r;   ty1 = ty0 + r;
            tz0 = gz * r2;  tz1 = tz0 + r2;
        } else {
            ty0 = gy * P1;  ty1 = ty0 + P1;
            tz0 = gz * P2;  tz1 = tz0 + P2;
        }

        float a0 = 0.0f, a1 = 0.0f;
        #pragma unroll
        for (int yz = 0; yz < 4; ++yz) {
            unsigned cy = (yz & 1) ? ty1 : ty0;
            unsigned cz = (yz & 2) ? tz1 : tz0;
            float wyz = ((yz & 1) ? ry : wy0) * ((yz & 2) ? rz : wz0);

            unsigned e0, e1;
            if (l < 6) {
                unsigned u = gx + cy + cz;              // under-hash, < 2*SIZE
                e0 = (u >= SIZE[l]) ? u - SIZE[l] : u;
                unsigned u1 = u + 1u;
                e1 = (u1 >= SIZE[l]) ? u1 - SIZE[l] : u1;
            } else {
                unsigned h = cy ^ cz;
                e0 = (gx ^ h) & HASH_MASK;
                e1 = ((gx + 1u) ^ h) & HASH_MASK;
            }
            unsigned base = e0 & ~1u;
            float4 q = __ldg(reinterpret_cast<const float4*>(
                                 tab2 + (OFF[l] + base)));
            float f0x = (e0 & 1u) ? q.z : q.x;
            float f0y = (e0 & 1u) ? q.w : q.y;
            float f1x, f1y;
            if ((e1 & ~1u) == base) {
                f1x = (e1 & 1u) ? q.z : q.x;
                f1y = (e1 & 1u) ? q.w : q.y;
            } else {
                float2 f1 = __ldg(tab2 + (OFF[l] + e1));
                f1x = f1.x; f1y = f1.y;
            }
            float wx0yz = wx0 * wyz;
            float rxyz  = rx  * wyz;
            a0 = fmaf(wx0yz, f0x, a0);
            a1 = fmaf(wx0yz, f0y, a1);
            a0 = fmaf(rxyz,  f1x, a0);
            a1 = fmaf(rxyz,  f1y, a1);
        }
        acc[2 * l]     = a0;
        acc[2 * l + 1] = a1;
    }

    // ---- Coalesced output via per-warp smem staging ----
    // Write phase: thread t -> s_stage row t (stride 33): bank (t + j) % 32,
    // conflict-free across the warp for each j.
    float* row = s_stage + tid * STRIDE;
    #pragma unroll
    for (int j = 0; j < 2 * NLEVELS; ++j)
        row[j] = acc[j];
    __syncwarp();

    // Copy phase: warp w drains its own 32 rows to out[p0*32 .. p0*32+1024).
    // Lane l handles float4 chunks: linear idx = k*128 + l*4, k = 0..7.
    // LDS (scalar): point-in-warp = 4k + l/8, feat = (4l)%32 ->
    // bank (l/8 + 4*(l%8) + 4k)%32, a bijection over lanes => conflict-free.
    // STG: 512B contiguous per warp-instruction (4 wavefronts vs 32).
    int warp = tid >> 5;
    int lane = tid & 31;
    long long p0 = (long long)blockIdx.x * blockDim.x + warp * 32;
    if (p0 < n) {  // full warps only (n divisible by 32 in this problem)
        const float* wbase = s_stage + (warp * 32) * STRIDE;
        float4* o4 = reinterpret_cast<float4*>(out + p0 * (2 * NLEVELS));
        #pragma unroll
        for (int k = 0; k < 8; ++k) {
            int linear = k * 128 + lane * 4;
            int pt   = linear >> 5;        // 0..31
            int feat = linear & 31;        // multiple of 4
            const float* src = wbase + pt * STRIDE + feat;
            float4 v = make_float4(src[0], src[1], src[2], src[3]);
            o4[k * 32 + lane] = v;
        }
    }
}

extern "C" void kernel_launch(void* const* d_in, const int* in_sizes, int n_in,
                              void* d_out, int out_size)
{
    const float* positions = (const float*)d_in[0];
    const float* table     = (const float*)d_in[1];
    if (n_in >= 2 && in_sizes[0] > in_sizes[1]) {
        positions = (const float*)d_in[1];
        table     = (const float*)d_in[0];
    }
    float* out = (float*)d_out;
    int n = (in_sizes[0] > in_sizes[1] ? in_sizes[1] : in_sizes[0]) / 3;

    int threads = 256;
    int blocks  = (n + threads - 1) / threads;
    hash_enc_kernel<<<blocks, threads>>>(positions, table, out, n);
}